// round 1
// baseline (speedup 1.0000x reference)
#include <cuda_runtime.h>
#include <math.h>

#define Bt 8
#define Nt 2048
#define Dt 128
#define BN 16384           // Bt*Nt
#define CAP 96             // max in/out degree capacity (mean ~20.5, sigma ~4.5)

// ---------------- scratch (static device allocations, allowed) ----------------
__device__ int   d_csc_cnt[BN];
__device__ int   d_csr_cnt[BN];
__device__ int   d_csc_idx[BN * CAP];
__device__ int   d_csr_idx[BN * CAP];
__device__ float d_agg [BN * Dt];
__device__ float d_h1  [BN * Dt];
__device__ float d_a1  [BN * Dt];
__device__ float d_hemb[BN * Dt];
__device__ float d_S   [BN * Dt];
__device__ float d_adjS[BN * Dt];
__device__ float d_StS [Bt * Dt * Dt];
__device__ double d_E, d_F, d_nnz, d_ent;

// ---------------- kernels ----------------

__global__ void k_clear(float* out, int osz) {
    int stride = gridDim.x * blockDim.x;
    int i0 = blockIdx.x * blockDim.x + threadIdx.x;
    for (int i = i0; i < BN; i += stride) { d_csc_cnt[i] = 0; d_csr_cnt[i] = 0; }
    for (int i = i0; i < Bt * Dt * Dt; i += stride) d_StS[i] = 0.f;
    for (int i = i0; i < osz; i += stride) out[i] = 0.f;
    if (i0 == 0) { d_E = 0.0; d_F = 0.0; d_nnz = 0.0; d_ent = 0.0; }
}

// one block per adjacency row (b,i); builds CSC (in-edges per target) and CSR (out-edges per source)
__global__ void k_build(const float* __restrict__ adj) {
    int row = blockIdx.x;                 // flat b*Nt + i
    int base = row & ~(Nt - 1);           // b*Nt
    const float* ar = adj + (size_t)row * Nt;
    for (int j = threadIdx.x; j < Nt; j += blockDim.x) {
        if (ar[j] != 0.0f) {
            int t = base + j;
            int p = atomicAdd(&d_csc_cnt[t], 1);
            if (p < CAP) d_csc_idx[t * CAP + p] = row;
            int q = atomicAdd(&d_csr_cnt[row], 1);
            if (q < CAP) d_csr_idx[row * CAP + q] = t;
        }
    }
}

// warp per output row: out[r,:] = (scale? 1/max(deg,1):1) * sum_{s in list[r]} X[s,:]
__global__ void k_spmm(const float* __restrict__ X, float* __restrict__ out,
                       int use_csr, int scale) {
    int warp = (blockIdx.x * blockDim.x + threadIdx.x) >> 5;
    int lane = threadIdx.x & 31;
    if (warp >= BN) return;
    const int* cntp = use_csr ? d_csr_cnt : d_csc_cnt;
    const int* idxp = use_csr ? d_csr_idx : d_csc_idx;
    int c = cntp[warp];
    int cl = c < CAP ? c : CAP;
    const int* ip = idxp + warp * CAP;
    float4 acc = make_float4(0.f, 0.f, 0.f, 0.f);
    for (int e = 0; e < cl; e++) {
        int s = ip[e];
        float4 v = *(const float4*)(X + (size_t)s * Dt + (lane << 2));
        acc.x += v.x; acc.y += v.y; acc.z += v.z; acc.w += v.w;
    }
    if (scale) {
        float sc = 1.0f / (float)(c > 1 ? c : 1);
        acc.x *= sc; acc.y *= sc; acc.z *= sc; acc.w *= sc;
    }
    *(float4*)(out + (size_t)warp * Dt + (lane << 2)) = acc;
}

// fused: out = l2norm(relu(agg @ Wl^T + b + xin @ Wr^T)) ; W are [128 out][128 in] row-major
#define LR 32
__global__ void k_linear(const float* __restrict__ agg, const float* __restrict__ xin,
                         const float* __restrict__ Wl, const float* __restrict__ bias,
                         const float* __restrict__ Wr, float* __restrict__ out) {
    __shared__ float in_s[LR][256];
    __shared__ float red[4][LR];
    int r0 = blockIdx.x * LR;
    for (int t = threadIdx.x; t < LR * 64; t += 128) {
        int r = t >> 6, k4 = (t & 63) << 2;
        float4 v;
        if (k4 < 128) v = *(const float4*)(agg + (size_t)(r0 + r) * Dt + k4);
        else          v = *(const float4*)(xin + (size_t)(r0 + r) * Dt + (k4 - 128));
        *(float4*)&in_s[r][k4] = v;
    }
    __syncthreads();
    int o = threadIdx.x;
    float acc[LR];
    float bv = bias[o];
#pragma unroll
    for (int r = 0; r < LR; r++) acc[r] = bv;

    const float* wl = Wl + o * Dt;
    for (int k = 0; k < Dt; k += 4) {
        float4 w = *(const float4*)(wl + k);
#pragma unroll
        for (int r = 0; r < LR; r++) {
            float4 iv = *(const float4*)&in_s[r][k];
            acc[r] += iv.x * w.x + iv.y * w.y + iv.z * w.z + iv.w * w.w;
        }
    }
    const float* wr = Wr + o * Dt;
    for (int k = 0; k < Dt; k += 4) {
        float4 w = *(const float4*)(wr + k);
#pragma unroll
        for (int r = 0; r < LR; r++) {
            float4 iv = *(const float4*)&in_s[r][128 + k];
            acc[r] += iv.x * w.x + iv.y * w.y + iv.z * w.z + iv.w * w.w;
        }
    }
    int wid = threadIdx.x >> 5, lane = threadIdx.x & 31;
#pragma unroll
    for (int r = 0; r < LR; r++) {
        float v = fmaxf(acc[r], 0.0f);
        acc[r] = v;
        float s = v * v;
#pragma unroll
        for (int off = 16; off; off >>= 1) s += __shfl_xor_sync(0xffffffffu, s, off);
        if (lane == 0) red[wid][r] = s;
    }
    __syncthreads();
#pragma unroll
    for (int r = 0; r < LR; r++) {
        float tot = red[0][r] + red[1][r] + red[2][r] + red[3][r];
        float iv = 1.0f / (sqrtf(tot) + 1e-9f);
        out[(size_t)(r0 + r) * Dt + o] = acc[r] * iv;
    }
}

// warp per row: in-place softmax over 128, accumulate entropy
__global__ void k_softmax_ent(float* __restrict__ S) {
    __shared__ float esm[8];
    int warp_l = threadIdx.x >> 5;
    int warp = (blockIdx.x * blockDim.x + threadIdx.x) >> 5;
    int lane = threadIdx.x & 31;
    float ent = 0.f;
    if (warp < BN) {
        float4 v = *(const float4*)(S + (size_t)warp * Dt + (lane << 2));
        float m = fmaxf(fmaxf(v.x, v.y), fmaxf(v.z, v.w));
#pragma unroll
        for (int off = 16; off; off >>= 1) m = fmaxf(m, __shfl_xor_sync(~0u, m, off));
        float e0 = expf(v.x - m), e1 = expf(v.y - m), e2 = expf(v.z - m), e3 = expf(v.w - m);
        float s = e0 + e1 + e2 + e3;
#pragma unroll
        for (int off = 16; off; off >>= 1) s += __shfl_xor_sync(~0u, s, off);
        float inv = 1.0f / s;
        float p0 = e0 * inv, p1 = e1 * inv, p2 = e2 * inv, p3 = e3 * inv;
        ent = -(p0 * logf(p0 + 1e-15f) + p1 * logf(p1 + 1e-15f)
              + p2 * logf(p2 + 1e-15f) + p3 * logf(p3 + 1e-15f));
#pragma unroll
        for (int off = 16; off; off >>= 1) ent += __shfl_xor_sync(~0u, ent, off);
        *(float4*)(S + (size_t)warp * Dt + (lane << 2)) = make_float4(p0, p1, p2, p3);
    }
    if (lane == 0) esm[warp_l] = ent;
    __syncthreads();
    if (threadIdx.x == 0) {
        float t = 0.f;
        for (int w = 0; w < 8; w++) t += esm[w];
        atomicAdd(&d_ent, (double)t);
    }
}

// C[b] += A[b]^T @ B[b]  (A,B: [Nt x 128] per batch, C: [128 x 128] per batch)
#define AR 32
#define AI 4
__global__ void k_atb(const float* __restrict__ A, const float* __restrict__ Bm,
                      float* __restrict__ C) {
    __shared__ float As[AR][Dt];
    __shared__ float Bs[AR][Dt];
    int b = blockIdx.y;
    float acc[8][8];
#pragma unroll
    for (int i = 0; i < 8; i++)
#pragma unroll
        for (int j = 0; j < 8; j++) acc[i][j] = 0.f;
    int tk = threadIdx.x >> 4, td = threadIdx.x & 15;
    for (int c = 0; c < AI; c++) {
        int n0 = (blockIdx.x * AI + c) * AR;
        const float* Ap = A  + ((size_t)b * Nt + n0) * Dt;
        const float* Bp = Bm + ((size_t)b * Nt + n0) * Dt;
        __syncthreads();
        for (int t = threadIdx.x; t < AR * 32; t += 256) {
            int r = t >> 5, k4 = (t & 31) << 2;
            *(float4*)&As[r][k4] = *(const float4*)(Ap + r * Dt + k4);
            *(float4*)&Bs[r][k4] = *(const float4*)(Bp + r * Dt + k4);
        }
        __syncthreads();
        for (int n = 0; n < AR; n++) {
            float a[8], bb[8];
            *(float4*)&a[0]  = *(const float4*)&As[n][tk * 8];
            *(float4*)&a[4]  = *(const float4*)&As[n][tk * 8 + 4];
            *(float4*)&bb[0] = *(const float4*)&Bs[n][td * 8];
            *(float4*)&bb[4] = *(const float4*)&Bs[n][td * 8 + 4];
#pragma unroll
            for (int i = 0; i < 8; i++)
#pragma unroll
                for (int j = 0; j < 8; j++) acc[i][j] += a[i] * bb[j];
        }
    }
    size_t cb = (size_t)b * Dt * Dt;
#pragma unroll
    for (int i = 0; i < 8; i++)
#pragma unroll
        for (int j = 0; j < 8; j++)
            atomicAdd(&C[cb + (size_t)(tk * 8 + i) * Dt + (td * 8 + j)], acc[i][j]);
}

// E = sum over edges (n->m) of dot(S[n], S[m]); warp per source row
__global__ void k_edgedot(const float* __restrict__ S) {
    __shared__ float esm[8];
    int warp_l = threadIdx.x >> 5;
    int warp = (blockIdx.x * blockDim.x + threadIdx.x) >> 5;
    int lane = threadIdx.x & 31;
    float loc = 0.f;
    if (warp < BN) {
        float4 sn = *(const float4*)(S + (size_t)warp * Dt + (lane << 2));
        int c = d_csr_cnt[warp]; if (c > CAP) c = CAP;
        const int* ip = d_csr_idx + warp * CAP;
        for (int e = 0; e < c; e++) {
            int mrow = ip[e];
            float4 sm = *(const float4*)(S + (size_t)mrow * Dt + (lane << 2));
            loc += sn.x * sm.x + sn.y * sm.y + sn.z * sm.z + sn.w * sm.w;
        }
#pragma unroll
        for (int off = 16; off; off >>= 1) loc += __shfl_xor_sync(~0u, loc, off);
    }
    if (lane == 0) esm[warp_l] = loc;
    __syncthreads();
    if (threadIdx.x == 0) {
        float t = 0.f;
        for (int w = 0; w < 8; w++) t += esm[w];
        atomicAdd(&d_E, (double)t);
    }
}

__global__ void k_sumcnt() {
    __shared__ float sm[8];
    int i = blockIdx.x * blockDim.x + threadIdx.x;
    float v = (i < BN) ? (float)d_csr_cnt[i] : 0.f;
#pragma unroll
    for (int off = 16; off; off >>= 1) v += __shfl_xor_sync(~0u, v, off);
    int wid = threadIdx.x >> 5, lane = threadIdx.x & 31;
    if (lane == 0) sm[wid] = v;
    __syncthreads();
    if (threadIdx.x == 0) {
        float t = 0.f;
        for (int w = 0; w < 8; w++) t += sm[w];
        atomicAdd(&d_nnz, (double)t);
    }
}

__global__ void k_sumsq() {
    __shared__ float sm[8];
    int i = blockIdx.x * blockDim.x + threadIdx.x;
    float x = (i < Bt * Dt * Dt) ? d_StS[i] : 0.f;
    float v = x * x;
#pragma unroll
    for (int off = 16; off; off >>= 1) v += __shfl_xor_sync(~0u, v, off);
    int wid = threadIdx.x >> 5, lane = threadIdx.x & 31;
    if (lane == 0) sm[wid] = v;
    __syncthreads();
    if (threadIdx.x == 0) {
        float t = 0.f;
        for (int w = 0; w < 8; w++) t += sm[w];
        atomicAdd(&d_F, (double)t);
    }
}

__global__ void k_final(float* out) {
    double l2 = d_nnz - 2.0 * d_E + d_F;
    if (l2 < 0.0) l2 = 0.0;
    out[2 * Bt * Dt * Dt]     = (float)(sqrt(l2) / ((double)Bt * Nt * Nt));
    out[2 * Bt * Dt * Dt + 1] = (float)(d_ent / (double)BN);
}

// ---------------- launch ----------------

extern "C" void kernel_launch(void* const* d_in, const int* in_sizes, int n_in,
                              void* d_out, int out_size) {
    const float* x    = (const float*)d_in[0];
    const float* adj  = (const float*)d_in[1];
    const float* We1l = (const float*)d_in[2];
    const float* be1  = (const float*)d_in[3];
    const float* We1r = (const float*)d_in[4];
    const float* We2l = (const float*)d_in[5];
    const float* be2  = (const float*)d_in[6];
    const float* We2r = (const float*)d_in[7];
    const float* Wa1l = (const float*)d_in[8];
    const float* ba1  = (const float*)d_in[9];
    const float* Wa1r = (const float*)d_in[10];
    const float* Wa2l = (const float*)d_in[11];
    const float* ba2  = (const float*)d_in[12];
    const float* Wa2r = (const float*)d_in[13];
    float* out = (float*)d_out;

    void* p;
    cudaGetSymbolAddress(&p, d_agg);  float* agg  = (float*)p;
    cudaGetSymbolAddress(&p, d_h1);   float* h1   = (float*)p;
    cudaGetSymbolAddress(&p, d_a1);   float* a1   = (float*)p;
    cudaGetSymbolAddress(&p, d_hemb); float* hemb = (float*)p;
    cudaGetSymbolAddress(&p, d_S);    float* S    = (float*)p;
    cudaGetSymbolAddress(&p, d_adjS); float* adjS = (float*)p;
    cudaGetSymbolAddress(&p, d_StS);  float* StS  = (float*)p;

    k_clear<<<256, 256>>>(out, out_size);
    k_build<<<BN, 256>>>(adj);

    // agg1 = adj^T x / deg  (shared by emb1 and assign1)
    k_spmm<<<BN / 8, 256>>>(x, agg, 0, 1);
    k_linear<<<BN / LR, 128>>>(agg, x, We1l, be1, We1r, h1);
    k_linear<<<BN / LR, 128>>>(agg, x, Wa1l, ba1, Wa1r, a1);

    // embedding block 2
    k_spmm<<<BN / 8, 256>>>(h1, agg, 0, 1);
    k_linear<<<BN / LR, 128>>>(agg, h1, We2l, be2, We2r, hemb);

    // assignment block 2
    k_spmm<<<BN / 8, 256>>>(a1, agg, 0, 1);
    k_linear<<<BN / LR, 128>>>(agg, a1, Wa2l, ba2, Wa2r, S);

    k_softmax_ent<<<BN / 8, 256>>>(S);

    // adjS = adj @ S (row gather via CSR, no scaling)
    k_spmm<<<BN / 8, 256>>>(S, adjS, 1, 0);

    // pooled outputs (atomic-accumulated, pre-zeroed)
    k_atb<<<dim3(Nt / (AR * AI), Bt), 256>>>(S, hemb, out);                   // h_pooled
    k_atb<<<dim3(Nt / (AR * AI), Bt), 256>>>(S, adjS, out + Bt * Dt * Dt);    // adj_pooled
    k_atb<<<dim3(Nt / (AR * AI), Bt), 256>>>(S, S, StS);                      // S^T S for link loss

    k_edgedot<<<BN / 8, 256>>>(S);
    k_sumcnt<<<BN / 256, 256>>>();
    k_sumsq<<<(Bt * Dt * Dt) / 256, 256>>>();
    k_final<<<1, 1>>>(out);
}

// round 2
// speedup vs baseline: 1.2548x; 1.2548x over previous
#include <cuda_runtime.h>
#include <math.h>

#define Bt 8
#define Nt 2048
#define Dt 128
#define BN 16384           // Bt*Nt
#define CAP 96             // max in/out degree capacity (mean ~20.5, sigma ~4.5)

typedef unsigned long long ull;

// ---------------- scratch (static device allocations, allowed) ----------------
__device__ int   d_csc_cnt[BN];
__device__ int   d_csr_cnt[BN];
__device__ int   d_csc_idx[BN * CAP];
__device__ int   d_csr_idx[BN * CAP];
__device__ float d_agg [BN * Dt];
__device__ float d_h1  [BN * Dt];
__device__ float d_a1  [BN * Dt];
__device__ float d_hemb[BN * Dt];
__device__ float d_S   [BN * Dt];
__device__ float d_adjS[BN * Dt];
__device__ float d_StS [Bt * Dt * Dt];
__device__ double d_E, d_F, d_nnz, d_ent;

// ---------------- kernels ----------------

__global__ void k_clear(float* out, int osz) {
    int stride = gridDim.x * blockDim.x;
    int i0 = blockIdx.x * blockDim.x + threadIdx.x;
    for (int i = i0; i < BN; i += stride) { d_csc_cnt[i] = 0; d_csr_cnt[i] = 0; }
    for (int i = i0; i < Bt * Dt * Dt; i += stride) d_StS[i] = 0.f;
    for (int i = i0; i < osz; i += stride) out[i] = 0.f;
    if (i0 == 0) { d_E = 0.0; d_F = 0.0; d_nnz = 0.0; d_ent = 0.0; }
}

// one block per adjacency row (b,i); builds CSC (in-edges per target) and CSR (out-edges per source)
__global__ void k_build(const float* __restrict__ adj) {
    int row = blockIdx.x;                 // flat b*Nt + i
    int base = row & ~(Nt - 1);           // b*Nt
    const float4* ar = (const float4*)(adj + (size_t)row * Nt);
    for (int j4 = threadIdx.x; j4 < Nt / 4; j4 += blockDim.x) {
        float4 v = ar[j4];
        int j = j4 << 2;
#pragma unroll
        for (int u = 0; u < 4; u++) {
            float f = (u == 0) ? v.x : (u == 1) ? v.y : (u == 2) ? v.z : v.w;
            if (f != 0.0f) {
                int t = base + j + u;
                int p = atomicAdd(&d_csc_cnt[t], 1);
                if (p < CAP) d_csc_idx[t * CAP + p] = row;
                int q = atomicAdd(&d_csr_cnt[row], 1);
                if (q < CAP) d_csr_idx[row * CAP + q] = t;
            }
        }
    }
}

// warp per output row: out[r,:] = (scale? 1/max(deg,1):1) * sum_{s in list[r]} X[s,:]
__global__ void k_spmm(const float* __restrict__ X, float* __restrict__ out,
                       int use_csr, int scale) {
    int warp = (blockIdx.x * blockDim.x + threadIdx.x) >> 5;
    int lane = threadIdx.x & 31;
    if (warp >= BN) return;
    const int* cntp = use_csr ? d_csr_cnt : d_csc_cnt;
    const int* idxp = use_csr ? d_csr_idx : d_csc_idx;
    int c = cntp[warp];
    int cl = c < CAP ? c : CAP;
    const int* ip = idxp + warp * CAP;
    float4 acc = make_float4(0.f, 0.f, 0.f, 0.f);
    int e = 0;
    for (; e + 2 <= cl; e += 2) {
        int s0 = ip[e], s1 = ip[e + 1];
        float4 v0 = *(const float4*)(X + (size_t)s0 * Dt + (lane << 2));
        float4 v1 = *(const float4*)(X + (size_t)s1 * Dt + (lane << 2));
        acc.x += v0.x + v1.x; acc.y += v0.y + v1.y;
        acc.z += v0.z + v1.z; acc.w += v0.w + v1.w;
    }
    if (e < cl) {
        int s = ip[e];
        float4 v = *(const float4*)(X + (size_t)s * Dt + (lane << 2));
        acc.x += v.x; acc.y += v.y; acc.z += v.z; acc.w += v.w;
    }
    if (scale) {
        float sc = 1.0f / (float)(c > 1 ? c : 1);
        acc.x *= sc; acc.y *= sc; acc.z *= sc; acc.w *= sc;
    }
    *(float4*)(out + (size_t)warp * Dt + (lane << 2)) = acc;
}

// fused dual-GEMM: out = l2norm(relu(agg @ Wl^T + b + xin @ Wr^T))
// Tiled SGEMM: 64 rows x 128 cols per block, 128 threads, 8x8 micro-tile,
// K=256 (agg|xin concat), 32-wide double-buffered smem tiles, packed f32x2 FMA.
#define TM 64
#define TK 32
__global__ void __launch_bounds__(128)
k_linear(const float* __restrict__ agg, const float* __restrict__ xin,
         const float* __restrict__ Wl, const float* __restrict__ bias,
         const float* __restrict__ Wr, float* __restrict__ out) {
    __shared__ float As[2][TK][TM];      // 16 KB  (k-major)
    __shared__ float Bs[2][TK][Dt];      // 32 KB  (k-major)

    int tx = threadIdx.x;
    int cg = tx & 15;            // col group: cols cg*8 .. cg*8+7
    int rg = tx >> 4;            // row group: rows rg*8 .. rg*8+7
    int r0 = blockIdx.x * TM;

    int aRow = tx >> 1;          // 0..63
    int aK0  = (tx & 1) * 16;    // 0 or 16

    ull acc[8][4];
#pragma unroll
    for (int i = 0; i < 8; i++)
#pragma unroll
        for (int j = 0; j < 4; j++) acc[i][j] = 0ull;

    float4 aReg[4], bReg[8];

    // ---- prologue: load tile 0 ----
    {
        const float* Asrc = agg;
        const float* Bsrc = Wl;
#pragma unroll
        for (int i = 0; i < 4; i++)
            aReg[i] = *(const float4*)(Asrc + (size_t)(r0 + aRow) * Dt + aK0 + 4 * i);
#pragma unroll
        for (int i = 0; i < 8; i++)
            bReg[i] = *(const float4*)(Bsrc + (size_t)tx * Dt + 4 * i);
#pragma unroll
        for (int i = 0; i < 4; i++) {
            int k = aK0 + 4 * i;
            As[0][k + 0][aRow] = aReg[i].x; As[0][k + 1][aRow] = aReg[i].y;
            As[0][k + 2][aRow] = aReg[i].z; As[0][k + 3][aRow] = aReg[i].w;
        }
#pragma unroll
        for (int i = 0; i < 8; i++) {
            int k = 4 * i;
            Bs[0][k + 0][tx] = bReg[i].x; Bs[0][k + 1][tx] = bReg[i].y;
            Bs[0][k + 2][tx] = bReg[i].z; Bs[0][k + 3][tx] = bReg[i].w;
        }
    }
    __syncthreads();

    for (int kt = 0; kt < 8; kt++) {
        int cur = kt & 1;
        if (kt < 7) {
            int nt = kt + 1;
            const float* Asrc = (nt < 4) ? agg : xin;
            const float* Bsrc = (nt < 4) ? Wl : Wr;
            int kb = (nt & 3) * TK;
#pragma unroll
            for (int i = 0; i < 4; i++)
                aReg[i] = *(const float4*)(Asrc + (size_t)(r0 + aRow) * Dt + kb + aK0 + 4 * i);
#pragma unroll
            for (int i = 0; i < 8; i++)
                bReg[i] = *(const float4*)(Bsrc + (size_t)tx * Dt + kb + 4 * i);
        }
        // ---- compute on buffer cur ----
#pragma unroll 4
        for (int kk = 0; kk < TK; kk++) {
            float4 a0 = *(const float4*)&As[cur][kk][rg * 8];
            float4 a1 = *(const float4*)&As[cur][kk][rg * 8 + 4];
            const ulonglong2* bp = (const ulonglong2*)&Bs[cur][kk][cg * 8];
            ulonglong2 b01 = bp[0];
            ulonglong2 b23 = bp[1];
            ull bv0 = b01.x, bv1 = b01.y, bv2 = b23.x, bv3 = b23.y;
            float av[8] = {a0.x, a0.y, a0.z, a0.w, a1.x, a1.y, a1.z, a1.w};
            ull ad[8];
#pragma unroll
            for (int i = 0; i < 8; i++) {
                unsigned int ab = __float_as_uint(av[i]);
                asm("mov.b64 %0, {%1, %1};" : "=l"(ad[i]) : "r"(ab));
            }
#pragma unroll
            for (int i = 0; i < 8; i++) {
                asm("fma.rn.f32x2 %0, %1, %2, %0;" : "+l"(acc[i][0]) : "l"(ad[i]), "l"(bv0));
                asm("fma.rn.f32x2 %0, %1, %2, %0;" : "+l"(acc[i][1]) : "l"(ad[i]), "l"(bv1));
                asm("fma.rn.f32x2 %0, %1, %2, %0;" : "+l"(acc[i][2]) : "l"(ad[i]), "l"(bv2));
                asm("fma.rn.f32x2 %0, %1, %2, %0;" : "+l"(acc[i][3]) : "l"(ad[i]), "l"(bv3));
            }
        }
        if (kt < 7) {
            int nxt = cur ^ 1;
#pragma unroll
            for (int i = 0; i < 4; i++) {
                int k = aK0 + 4 * i;
                As[nxt][k + 0][aRow] = aReg[i].x; As[nxt][k + 1][aRow] = aReg[i].y;
                As[nxt][k + 2][aRow] = aReg[i].z; As[nxt][k + 3][aRow] = aReg[i].w;
            }
#pragma unroll
            for (int i = 0; i < 8; i++) {
                int k = 4 * i;
                Bs[nxt][k + 0][tx] = bReg[i].x; Bs[nxt][k + 1][tx] = bReg[i].y;
                Bs[nxt][k + 2][tx] = bReg[i].z; Bs[nxt][k + 3][tx] = bReg[i].w;
            }
            __syncthreads();
        }
    }

    // ---- epilogue: bias + relu + row L2-norm ----
    __syncthreads();                     // everyone done with As; alias it as reduction buffer
    float* red = &As[0][0][0];           // [64][16]

    float bias8[8];
#pragma unroll
    for (int j = 0; j < 8; j++) bias8[j] = bias[cg * 8 + j];

    float v[8][8];
#pragma unroll
    for (int i = 0; i < 8; i++) {
        float ss = 0.f;
#pragma unroll
        for (int jp = 0; jp < 4; jp++) {
            float lo, hi;
            asm("mov.b64 {%0, %1}, %2;" : "=f"(lo), "=f"(hi) : "l"(acc[i][jp]));
            lo = fmaxf(lo + bias8[2 * jp], 0.f);
            hi = fmaxf(hi + bias8[2 * jp + 1], 0.f);
            v[i][2 * jp] = lo; v[i][2 * jp + 1] = hi;
            ss += lo * lo + hi * hi;
        }
        red[(rg * 8 + i) * 16 + cg] = ss;
    }
    __syncthreads();
#pragma unroll
    for (int i = 0; i < 8; i++) {
        int rl = rg * 8 + i;
        float tot = 0.f;
#pragma unroll
        for (int t = 0; t < 16; t++) tot += red[rl * 16 + t];
        float inv = 1.0f / (sqrtf(tot) + 1e-9f);
        float* op = out + (size_t)(r0 + rl) * Dt + cg * 8;
        float4 o0 = make_float4(v[i][0] * inv, v[i][1] * inv, v[i][2] * inv, v[i][3] * inv);
        float4 o1 = make_float4(v[i][4] * inv, v[i][5] * inv, v[i][6] * inv, v[i][7] * inv);
        *(float4*)op = o0;
        *(float4*)(op + 4) = o1;
    }
}

// warp per row: in-place softmax over 128, accumulate entropy
__global__ void k_softmax_ent(float* __restrict__ S) {
    __shared__ float esm[8];
    int warp_l = threadIdx.x >> 5;
    int warp = (blockIdx.x * blockDim.x + threadIdx.x) >> 5;
    int lane = threadIdx.x & 31;
    float ent = 0.f;
    if (warp < BN) {
        float4 v = *(const float4*)(S + (size_t)warp * Dt + (lane << 2));
        float m = fmaxf(fmaxf(v.x, v.y), fmaxf(v.z, v.w));
#pragma unroll
        for (int off = 16; off; off >>= 1) m = fmaxf(m, __shfl_xor_sync(~0u, m, off));
        float e0 = expf(v.x - m), e1 = expf(v.y - m), e2 = expf(v.z - m), e3 = expf(v.w - m);
        float s = e0 + e1 + e2 + e3;
#pragma unroll
        for (int off = 16; off; off >>= 1) s += __shfl_xor_sync(~0u, s, off);
        float inv = 1.0f / s;
        float p0 = e0 * inv, p1 = e1 * inv, p2 = e2 * inv, p3 = e3 * inv;
        ent = -(p0 * logf(p0 + 1e-15f) + p1 * logf(p1 + 1e-15f)
              + p2 * logf(p2 + 1e-15f) + p3 * logf(p3 + 1e-15f));
#pragma unroll
        for (int off = 16; off; off >>= 1) ent += __shfl_xor_sync(~0u, ent, off);
        *(float4*)(S + (size_t)warp * Dt + (lane << 2)) = make_float4(p0, p1, p2, p3);
    }
    if (lane == 0) esm[warp_l] = ent;
    __syncthreads();
    if (threadIdx.x == 0) {
        float t = 0.f;
        for (int w = 0; w < 8; w++) t += esm[w];
        atomicAdd(&d_ent, (double)t);
    }
}

// C[b] += A[b]^T @ B[b]  (A,B: [Nt x 128] per batch, C: [128 x 128] per batch)
#define AR 32
#define AI 4
__global__ void k_atb(const float* __restrict__ A, const float* __restrict__ Bm,
                      float* __restrict__ C) {
    __shared__ float As[AR][Dt];
    __shared__ float Bs[AR][Dt];
    int b = blockIdx.y;
    float acc[8][8];
#pragma unroll
    for (int i = 0; i < 8; i++)
#pragma unroll
        for (int j = 0; j < 8; j++) acc[i][j] = 0.f;
    int tk = threadIdx.x >> 4, td = threadIdx.x & 15;
    for (int c = 0; c < AI; c++) {
        int n0 = (blockIdx.x * AI + c) * AR;
        const float* Ap = A  + ((size_t)b * Nt + n0) * Dt;
        const float* Bp = Bm + ((size_t)b * Nt + n0) * Dt;
        __syncthreads();
        for (int t = threadIdx.x; t < AR * 32; t += 256) {
            int r = t >> 5, k4 = (t & 31) << 2;
            *(float4*)&As[r][k4] = *(const float4*)(Ap + r * Dt + k4);
            *(float4*)&Bs[r][k4] = *(const float4*)(Bp + r * Dt + k4);
        }
        __syncthreads();
        for (int n = 0; n < AR; n++) {
            float a[8], bb[8];
            *(float4*)&a[0]  = *(const float4*)&As[n][tk * 8];
            *(float4*)&a[4]  = *(const float4*)&As[n][tk * 8 + 4];
            *(float4*)&bb[0] = *(const float4*)&Bs[n][td * 8];
            *(float4*)&bb[4] = *(const float4*)&Bs[n][td * 8 + 4];
#pragma unroll
            for (int i = 0; i < 8; i++)
#pragma unroll
                for (int j = 0; j < 8; j++) acc[i][j] += a[i] * bb[j];
        }
    }
    size_t cb = (size_t)b * Dt * Dt;
#pragma unroll
    for (int i = 0; i < 8; i++)
#pragma unroll
        for (int j = 0; j < 8; j++)
            atomicAdd(&C[cb + (size_t)(tk * 8 + i) * Dt + (td * 8 + j)], acc[i][j]);
}

// E = sum over edges (n->m) of dot(S[n], S[m]); warp per source row
__global__ void k_edgedot(const float* __restrict__ S) {
    __shared__ float esm[8];
    int warp_l = threadIdx.x >> 5;
    int warp = (blockIdx.x * blockDim.x + threadIdx.x) >> 5;
    int lane = threadIdx.x & 31;
    float loc = 0.f;
    if (warp < BN) {
        float4 sn = *(const float4*)(S + (size_t)warp * Dt + (lane << 2));
        int c = d_csr_cnt[warp]; if (c > CAP) c = CAP;
        const int* ip = d_csr_idx + warp * CAP;
        for (int e = 0; e < c; e++) {
            int mrow = ip[e];
            float4 sm = *(const float4*)(S + (size_t)mrow * Dt + (lane << 2));
            loc += sn.x * sm.x + sn.y * sm.y + sn.z * sm.z + sn.w * sm.w;
        }
#pragma unroll
        for (int off = 16; off; off >>= 1) loc += __shfl_xor_sync(~0u, loc, off);
    }
    if (lane == 0) esm[warp_l] = loc;
    __syncthreads();
    if (threadIdx.x == 0) {
        float t = 0.f;
        for (int w = 0; w < 8; w++) t += esm[w];
        atomicAdd(&d_E, (double)t);
    }
}

__global__ void k_sumcnt() {
    __shared__ float sm[8];
    int i = blockIdx.x * blockDim.x + threadIdx.x;
    float v = (i < BN) ? (float)d_csr_cnt[i] : 0.f;
#pragma unroll
    for (int off = 16; off; off >>= 1) v += __shfl_xor_sync(~0u, v, off);
    int wid = threadIdx.x >> 5, lane = threadIdx.x & 31;
    if (lane == 0) sm[wid] = v;
    __syncthreads();
    if (threadIdx.x == 0) {
        float t = 0.f;
        for (int w = 0; w < 8; w++) t += sm[w];
        atomicAdd(&d_nnz, (double)t);
    }
}

__global__ void k_sumsq() {
    __shared__ float sm[8];
    int i = blockIdx.x * blockDim.x + threadIdx.x;
    float x = (i < Bt * Dt * Dt) ? d_StS[i] : 0.f;
    float v = x * x;
#pragma unroll
    for (int off = 16; off; off >>= 1) v += __shfl_xor_sync(~0u, v, off);
    int wid = threadIdx.x >> 5, lane = threadIdx.x & 31;
    if (lane == 0) sm[wid] = v;
    __syncthreads();
    if (threadIdx.x == 0) {
        float t = 0.f;
        for (int w = 0; w < 8; w++) t += sm[w];
        atomicAdd(&d_F, (double)t);
    }
}

__global__ void k_final(float* out) {
    double l2 = d_nnz - 2.0 * d_E + d_F;
    if (l2 < 0.0) l2 = 0.0;
    out[2 * Bt * Dt * Dt]     = (float)(sqrt(l2) / ((double)Bt * Nt * Nt));
    out[2 * Bt * Dt * Dt + 1] = (float)(d_ent / (double)BN);
}

// ---------------- launch ----------------

extern "C" void kernel_launch(void* const* d_in, const int* in_sizes, int n_in,
                              void* d_out, int out_size) {
    const float* x    = (const float*)d_in[0];
    const float* adj  = (const float*)d_in[1];
    const float* We1l = (const float*)d_in[2];
    const float* be1  = (const float*)d_in[3];
    const float* We1r = (const float*)d_in[4];
    const float* We2l = (const float*)d_in[5];
    const float* be2  = (const float*)d_in[6];
    const float* We2r = (const float*)d_in[7];
    const float* Wa1l = (const float*)d_in[8];
    const float* ba1  = (const float*)d_in[9];
    const float* Wa1r = (const float*)d_in[10];
    const float* Wa2l = (const float*)d_in[11];
    const float* ba2  = (const float*)d_in[12];
    const float* Wa2r = (const float*)d_in[13];
    float* out = (float*)d_out;

    void* p;
    cudaGetSymbolAddress(&p, d_agg);  float* agg  = (float*)p;
    cudaGetSymbolAddress(&p, d_h1);   float* h1   = (float*)p;
    cudaGetSymbolAddress(&p, d_a1);   float* a1   = (float*)p;
    cudaGetSymbolAddress(&p, d_hemb); float* hemb = (float*)p;
    cudaGetSymbolAddress(&p, d_S);    float* S    = (float*)p;
    cudaGetSymbolAddress(&p, d_adjS); float* adjS = (float*)p;
    cudaGetSymbolAddress(&p, d_StS);  float* StS  = (float*)p;

    k_clear<<<256, 256>>>(out, out_size);
    k_build<<<BN, 256>>>(adj);

    // agg1 = adj^T x / deg  (shared by emb1 and assign1)
    k_spmm<<<BN / 8, 256>>>(x, agg, 0, 1);
    k_linear<<<BN / TM, 128>>>(agg, x, We1l, be1, We1r, h1);
    k_linear<<<BN / TM, 128>>>(agg, x, Wa1l, ba1, Wa1r, a1);

    // embedding block 2
    k_spmm<<<BN / 8, 256>>>(h1, agg, 0, 1);
    k_linear<<<BN / TM, 128>>>(agg, h1, We2l, be2, We2r, hemb);

    // assignment block 2
    k_spmm<<<BN / 8, 256>>>(a1, agg, 0, 1);
    k_linear<<<BN / TM, 128>>>(agg, a1, Wa2l, ba2, Wa2r, S);

    k_softmax_ent<<<BN / 8, 256>>>(S);

    // adjS = adj @ S (row gather via CSR, no scaling)
    k_spmm<<<BN / 8, 256>>>(S, adjS, 1, 0);

    // pooled outputs (atomic-accumulated, pre-zeroed)
    k_atb<<<dim3(Nt / (AR * AI), Bt), 256>>>(S, hemb, out);                   // h_pooled
    k_atb<<<dim3(Nt / (AR * AI), Bt), 256>>>(S, adjS, out + Bt * Dt * Dt);    // adj_pooled
    k_atb<<<dim3(Nt / (AR * AI), Bt), 256>>>(S, S, StS);                      // S^T S for link loss

    k_edgedot<<<BN / 8, 256>>>(S);
    k_sumcnt<<<BN / 256, 256>>>();
    k_sumsq<<<(Bt * Dt * Dt) / 256, 256>>>();
    k_final<<<1, 1>>>(out);
}

// round 4
// speedup vs baseline: 1.2967x; 1.0334x over previous
#include <cuda_runtime.h>
#include <math.h>

#define Bt 8
#define Nt 2048
#define Dt 128
#define BN 16384           // Bt*Nt
#define CAP 96             // max in/out degree capacity (mean ~20.5, sigma ~4.5)

typedef unsigned long long ull;

// ---------------- scratch (static device allocations, allowed) ----------------
__device__ int   d_csc_cnt[BN];
__device__ int   d_csr_cnt[BN];
__device__ int   d_csc_idx[BN * CAP];
__device__ int   d_csr_idx[BN * CAP];
__device__ float d_agg [BN * Dt];
__device__ float d_h1  [BN * Dt];
__device__ float d_a1  [BN * Dt];
__device__ float d_hemb[BN * Dt];
__device__ float d_S   [BN * Dt];
__device__ float d_adjS[BN * Dt];
__device__ float d_StS [Bt * Dt * Dt];
__device__ double d_E, d_F, d_nnz, d_ent;

// ---------------- kernels ----------------

__global__ void k_clear(float* out, int osz) {
    int stride = gridDim.x * blockDim.x;
    int i0 = blockIdx.x * blockDim.x + threadIdx.x;
    for (int i = i0; i < BN; i += stride) { d_csc_cnt[i] = 0; d_csr_cnt[i] = 0; }
    for (int i = i0; i < Bt * Dt * Dt; i += stride) d_StS[i] = 0.f;
    for (int i = i0; i < osz; i += stride) out[i] = 0.f;
    if (i0 == 0) { d_E = 0.0; d_F = 0.0; d_nnz = 0.0; d_ent = 0.0; }
}

// one block per adjacency row (b,i); builds CSC (in-edges per target) and CSR (out-edges per source)
__global__ void k_build(const float* __restrict__ adj) {
    int row = blockIdx.x;                 // flat b*Nt + i
    int base = row & ~(Nt - 1);           // b*Nt
    const float4* ar = (const float4*)(adj + (size_t)row * Nt);
    for (int j4 = threadIdx.x; j4 < Nt / 4; j4 += blockDim.x) {
        float4 v = ar[j4];
        int j = j4 << 2;
#pragma unroll
        for (int u = 0; u < 4; u++) {
            float f = (u == 0) ? v.x : (u == 1) ? v.y : (u == 2) ? v.z : v.w;
            if (f != 0.0f) {
                int t = base + j + u;
                int p = atomicAdd(&d_csc_cnt[t], 1);
                if (p < CAP) d_csc_idx[t * CAP + p] = row;
                int q = atomicAdd(&d_csr_cnt[row], 1);
                if (q < CAP) d_csr_idx[row * CAP + q] = t;
            }
        }
    }
}

// warp per output row: out[r,:] = (scale? 1/max(deg,1):1) * sum_{s in list[r]} X[s,:]
__global__ void k_spmm(const float* __restrict__ X, float* __restrict__ out,
                       int use_csr, int scale) {
    int warp = (blockIdx.x * blockDim.x + threadIdx.x) >> 5;
    int lane = threadIdx.x & 31;
    if (warp >= BN) return;
    const int* cntp = use_csr ? d_csr_cnt : d_csc_cnt;
    const int* idxp = use_csr ? d_csr_idx : d_csc_idx;
    int c = cntp[warp];
    int cl = c < CAP ? c : CAP;
    const int* ip = idxp + warp * CAP;
    float4 acc = make_float4(0.f, 0.f, 0.f, 0.f);
    int e = 0;
    for (; e + 2 <= cl; e += 2) {
        int s0 = ip[e], s1 = ip[e + 1];
        float4 v0 = *(const float4*)(X + (size_t)s0 * Dt + (lane << 2));
        float4 v1 = *(const float4*)(X + (size_t)s1 * Dt + (lane << 2));
        acc.x += v0.x + v1.x; acc.y += v0.y + v1.y;
        acc.z += v0.z + v1.z; acc.w += v0.w + v1.w;
    }
    if (e < cl) {
        int s = ip[e];
        float4 v = *(const float4*)(X + (size_t)s * Dt + (lane << 2));
        acc.x += v.x; acc.y += v.y; acc.z += v.z; acc.w += v.w;
    }
    if (scale) {
        float sc = 1.0f / (float)(c > 1 ? c : 1);
        acc.x *= sc; acc.y *= sc; acc.z *= sc; acc.w *= sc;
    }
    *(float4*)(out + (size_t)warp * Dt + (lane << 2)) = acc;
}

// ---------------------------------------------------------------------------
// fused dual-GEMM via tf32x2 tensor cores (3-MMA error-compensated split):
//   out = l2norm(relu(agg @ Wl^T + b + xin @ Wr^T))
// Block: 128 rows x 128 cols, 256 threads = 8 warps (2M x 4N), warp 64x32.
// mma.sync.m16n8k8 tf32, acc += Ah*Bh + Ah*Bl + Al*Bh.
// smem: uint2 (hi,lo) per element, row stride 20 uint2 (40 words) => the
// 64-bit fragment LDS is conflict-free in each 16-lane phase.
// A fragment order (PTX): a0=(g,k) a1=(g+8,k) a2=(g,k+4) a3=(g+8,k+4).
// ---------------------------------------------------------------------------
#define KSTR 20
#define MMA_TF32(ac, a0, a1, a2, a3, b0, b1) \
    asm volatile("mma.sync.aligned.m16n8k8.row.col.f32.tf32.tf32.f32 " \
        "{%0,%1,%2,%3}, {%4,%5,%6,%7}, {%8,%9}, {%0,%1,%2,%3};" \
        : "+f"((ac)[0]), "+f"((ac)[1]), "+f"((ac)[2]), "+f"((ac)[3]) \
        : "r"(a0), "r"(a1), "r"(a2), "r"(a3), "r"(b0), "r"(b1))

__device__ __forceinline__ uint2 split_tf32(float v) {
    unsigned hi, lo;
    asm("cvt.rna.tf32.f32 %0, %1;" : "=r"(hi) : "f"(v));
    float rem = v - __uint_as_float(hi);
    asm("cvt.rna.tf32.f32 %0, %1;" : "=r"(lo) : "f"(rem));
    return make_uint2(hi, lo);
}

__global__ void __launch_bounds__(256)
k_linear(const float* __restrict__ agg, const float* __restrict__ xin,
         const float* __restrict__ Wl, const float* __restrict__ bias,
         const float* __restrict__ Wr, float* __restrict__ out) {
    __shared__ uint2 As2[128 * KSTR];    // 20 KB
    __shared__ uint2 Bs2[128 * KSTR];    // 20 KB

    int tx = threadIdx.x;
    int lane = tx & 31;
    int warp = tx >> 5;
    int warpM = warp >> 2;        // 0..1 : rows warpM*64 .. +63
    int warpN = warp & 3;         // 0..3 : cols warpN*32 .. +31
    int lq = lane >> 2;           // 0..7
    int lr = lane & 3;            // 0..3
    int r0 = blockIdx.x * 128;

    float acc[4][4][4];
#pragma unroll
    for (int mi = 0; mi < 4; mi++)
#pragma unroll
        for (int nj = 0; nj < 4; nj++)
#pragma unroll
            for (int q = 0; q < 4; q++) acc[mi][nj][q] = 0.f;

    for (int kc = 0; kc < 16; kc++) {           // 16 chunks of K=16
        const float* Asrc = (kc < 8) ? agg : xin;
        const float* Bsrc = (kc < 8) ? Wl : Wr;
        int kb = (kc & 7) * 16;
        // load chunk: 128 rows x 4 float4 each for A and B (512 float4 each)
#pragma unroll
        for (int it = 0; it < 2; it++) {
            int i = tx + it * 256;
            int row = i >> 2, k4 = (i & 3) << 2;
            float4 va = *(const float4*)(Asrc + (size_t)(r0 + row) * Dt + kb + k4);
            float4 vb = *(const float4*)(Bsrc + (size_t)row * Dt + kb + k4);
            uint2* ap = &As2[row * KSTR + k4];
            uint2* bp = &Bs2[row * KSTR + k4];
            ap[0] = split_tf32(va.x); ap[1] = split_tf32(va.y);
            ap[2] = split_tf32(va.z); ap[3] = split_tf32(va.w);
            bp[0] = split_tf32(vb.x); bp[1] = split_tf32(vb.y);
            bp[2] = split_tf32(vb.z); bp[3] = split_tf32(vb.w);
        }
        __syncthreads();
#pragma unroll
        for (int ks = 0; ks < 2; ks++) {
            int k0 = ks * 8;
            uint2 af[4][4];
#pragma unroll
            for (int mi = 0; mi < 4; mi++) {
                int row = warpM * 64 + mi * 16 + lq;
                af[mi][0] = As2[row * KSTR + k0 + lr];            // (g,   k)
                af[mi][1] = As2[(row + 8) * KSTR + k0 + lr];      // (g+8, k)
                af[mi][2] = As2[row * KSTR + k0 + 4 + lr];        // (g,   k+4)
                af[mi][3] = As2[(row + 8) * KSTR + k0 + 4 + lr];  // (g+8, k+4)
            }
            uint2 bf[4][2];
#pragma unroll
            for (int nj = 0; nj < 4; nj++) {
                int n = warpN * 32 + nj * 8 + lq;
                bf[nj][0] = Bs2[n * KSTR + k0 + lr];
                bf[nj][1] = Bs2[n * KSTR + k0 + 4 + lr];
            }
#pragma unroll
            for (int mi = 0; mi < 4; mi++)
#pragma unroll
                for (int nj = 0; nj < 4; nj++) {
                    MMA_TF32(acc[mi][nj],
                             af[mi][0].x, af[mi][1].x, af[mi][2].x, af[mi][3].x,
                             bf[nj][0].x, bf[nj][1].x);
                    MMA_TF32(acc[mi][nj],
                             af[mi][0].x, af[mi][1].x, af[mi][2].x, af[mi][3].x,
                             bf[nj][0].y, bf[nj][1].y);
                    MMA_TF32(acc[mi][nj],
                             af[mi][0].y, af[mi][1].y, af[mi][2].y, af[mi][3].y,
                             bf[nj][0].x, bf[nj][1].x);
                }
        }
        __syncthreads();
    }

    // ---- epilogue: bias + relu + row L2 norm ----
    float* red = (float*)As2;             // [128][4]

    float bv[4][2];
#pragma unroll
    for (int nj = 0; nj < 4; nj++) {
        int col = warpN * 32 + nj * 8 + 2 * lr;
        bv[nj][0] = bias[col];
        bv[nj][1] = bias[col + 1];
    }

    float ss[4][2];
#pragma unroll
    for (int mi = 0; mi < 4; mi++) { ss[mi][0] = 0.f; ss[mi][1] = 0.f; }
#pragma unroll
    for (int mi = 0; mi < 4; mi++)
#pragma unroll
        for (int nj = 0; nj < 4; nj++) {
            float v0 = fmaxf(acc[mi][nj][0] + bv[nj][0], 0.f);
            float v1 = fmaxf(acc[mi][nj][1] + bv[nj][1], 0.f);
            float v2 = fmaxf(acc[mi][nj][2] + bv[nj][0], 0.f);
            float v3 = fmaxf(acc[mi][nj][3] + bv[nj][1], 0.f);
            acc[mi][nj][0] = v0; acc[mi][nj][1] = v1;
            acc[mi][nj][2] = v2; acc[mi][nj][3] = v3;
            ss[mi][0] += v0 * v0 + v1 * v1;
            ss[mi][1] += v2 * v2 + v3 * v3;
        }
    // reduce across the 4 lanes of each quad (same lq, different lr)
#pragma unroll
    for (int mi = 0; mi < 4; mi++)
#pragma unroll
        for (int h = 0; h < 2; h++) {
            float s = ss[mi][h];
            s += __shfl_xor_sync(~0u, s, 1);
            s += __shfl_xor_sync(~0u, s, 2);
            ss[mi][h] = s;
        }
    if (lr == 0) {
#pragma unroll
        for (int mi = 0; mi < 4; mi++)
#pragma unroll
            for (int h = 0; h < 2; h++) {
                int row = warpM * 64 + mi * 16 + lq + h * 8;
                red[row * 4 + warpN] = ss[mi][h];
            }
    }
    __syncthreads();
#pragma unroll
    for (int mi = 0; mi < 4; mi++) {
        int rowA = warpM * 64 + mi * 16 + lq;
        float t0 = red[rowA * 4] + red[rowA * 4 + 1] + red[rowA * 4 + 2] + red[rowA * 4 + 3];
        float t1 = red[(rowA + 8) * 4] + red[(rowA + 8) * 4 + 1] + red[(rowA + 8) * 4 + 2] + red[(rowA + 8) * 4 + 3];
        float inv0 = 1.0f / (sqrtf(t0) + 1e-9f);
        float inv1 = 1.0f / (sqrtf(t1) + 1e-9f);
#pragma unroll
        for (int nj = 0; nj < 4; nj++) {
            int col = warpN * 32 + nj * 8 + 2 * lr;
            float2 o0 = make_float2(acc[mi][nj][0] * inv0, acc[mi][nj][1] * inv0);
            float2 o1 = make_float2(acc[mi][nj][2] * inv1, acc[mi][nj][3] * inv1);
            *(float2*)(out + (size_t)(r0 + rowA) * Dt + col) = o0;
            *(float2*)(out + (size_t)(r0 + rowA + 8) * Dt + col) = o1;
        }
    }
}

// warp per row: in-place softmax over 128, accumulate entropy
__global__ void k_softmax_ent(float* __restrict__ S) {
    __shared__ float esm[8];
    int warp_l = threadIdx.x >> 5;
    int warp = (blockIdx.x * blockDim.x + threadIdx.x) >> 5;
    int lane = threadIdx.x & 31;
    float ent = 0.f;
    if (warp < BN) {
        float4 v = *(const float4*)(S + (size_t)warp * Dt + (lane << 2));
        float m = fmaxf(fmaxf(v.x, v.y), fmaxf(v.z, v.w));
#pragma unroll
        for (int off = 16; off; off >>= 1) m = fmaxf(m, __shfl_xor_sync(~0u, m, off));
        float e0 = expf(v.x - m), e1 = expf(v.y - m), e2 = expf(v.z - m), e3 = expf(v.w - m);
        float s = e0 + e1 + e2 + e3;
#pragma unroll
        for (int off = 16; off; off >>= 1) s += __shfl_xor_sync(~0u, s, off);
        float inv = 1.0f / s;
        float p0 = e0 * inv, p1 = e1 * inv, p2 = e2 * inv, p3 = e3 * inv;
        ent = -(p0 * logf(p0 + 1e-15f) + p1 * logf(p1 + 1e-15f)
              + p2 * logf(p2 + 1e-15f) + p3 * logf(p3 + 1e-15f));
#pragma unroll
        for (int off = 16; off; off >>= 1) ent += __shfl_xor_sync(~0u, ent, off);
        *(float4*)(S + (size_t)warp * Dt + (lane << 2)) = make_float4(p0, p1, p2, p3);
    }
    if (lane == 0) esm[warp_l] = ent;
    __syncthreads();
    if (threadIdx.x == 0) {
        float t = 0.f;
        for (int w = 0; w < 8; w++) t += esm[w];
        atomicAdd(&d_ent, (double)t);
    }
}

// C[b] += A[b]^T @ B[b]  (A,B: [Nt x 128] per batch, C: [128 x 128] per batch)
#define AR 32
#define AI 4
__global__ void k_atb(const float* __restrict__ A, const float* __restrict__ Bm,
                      float* __restrict__ C) {
    __shared__ float As[AR][Dt];
    __shared__ float Bs[AR][Dt];
    int b = blockIdx.y;
    ull acc[8][4];
#pragma unroll
    for (int i = 0; i < 8; i++)
#pragma unroll
        for (int j = 0; j < 4; j++) acc[i][j] = 0ull;
    int tk = threadIdx.x >> 4, td = threadIdx.x & 15;
    for (int c = 0; c < AI; c++) {
        int n0 = (blockIdx.x * AI + c) * AR;
        const float* Ap = A  + ((size_t)b * Nt + n0) * Dt;
        const float* Bp = Bm + ((size_t)b * Nt + n0) * Dt;
        __syncthreads();
        for (int t = threadIdx.x; t < AR * 32; t += 256) {
            int r = t >> 5, k4 = (t & 31) << 2;
            *(float4*)&As[r][k4] = *(const float4*)(Ap + r * Dt + k4);
            *(float4*)&Bs[r][k4] = *(const float4*)(Bp + r * Dt + k4);
        }
        __syncthreads();
        for (int n = 0; n < AR; n++) {
            float a[8];
            *(float4*)&a[0] = *(const float4*)&As[n][tk * 8];
            *(float4*)&a[4] = *(const float4*)&As[n][tk * 8 + 4];
            const ulonglong2* bp = (const ulonglong2*)&Bs[n][td * 8];
            ulonglong2 b01 = bp[0];
            ulonglong2 b23 = bp[1];
            ull ad[8];
#pragma unroll
            for (int i = 0; i < 8; i++) {
                unsigned int ab = __float_as_uint(a[i]);
                asm("mov.b64 %0, {%1, %1};" : "=l"(ad[i]) : "r"(ab));
            }
#pragma unroll
            for (int i = 0; i < 8; i++) {
                asm("fma.rn.f32x2 %0, %1, %2, %0;" : "+l"(acc[i][0]) : "l"(ad[i]), "l"(b01.x));
                asm("fma.rn.f32x2 %0, %1, %2, %0;" : "+l"(acc[i][1]) : "l"(ad[i]), "l"(b01.y));
                asm("fma.rn.f32x2 %0, %1, %2, %0;" : "+l"(acc[i][2]) : "l"(ad[i]), "l"(b23.x));
                asm("fma.rn.f32x2 %0, %1, %2, %0;" : "+l"(acc[i][3]) : "l"(ad[i]), "l"(b23.y));
            }
        }
    }
    size_t cb = (size_t)b * Dt * Dt;
#pragma unroll
    for (int i = 0; i < 8; i++)
#pragma unroll
        for (int j = 0; j < 4; j++) {
            float lo, hi;
            asm("mov.b64 {%0, %1}, %2;" : "=f"(lo), "=f"(hi) : "l"(acc[i][j]));
            atomicAdd(&C[cb + (size_t)(tk * 8 + i) * Dt + (td * 8 + 2 * j)], lo);
            atomicAdd(&C[cb + (size_t)(tk * 8 + i) * Dt + (td * 8 + 2 * j + 1)], hi);
        }
}

// E = sum over edges (n->m) of dot(S[n], S[m]); warp per source row
__global__ void k_edgedot(const float* __restrict__ S) {
    __shared__ float esm[8];
    int warp_l = threadIdx.x >> 5;
    int warp = (blockIdx.x * blockDim.x + threadIdx.x) >> 5;
    int lane = threadIdx.x & 31;
    float loc = 0.f;
    if (warp < BN) {
        float4 sn = *(const float4*)(S + (size_t)warp * Dt + (lane << 2));
        int c = d_csr_cnt[warp]; if (c > CAP) c = CAP;
        const int* ip = d_csr_idx + warp * CAP;
        for (int e = 0; e < c; e++) {
            int mrow = ip[e];
            float4 sm = *(const float4*)(S + (size_t)mrow * Dt + (lane << 2));
            loc += sn.x * sm.x + sn.y * sm.y + sn.z * sm.z + sn.w * sm.w;
        }
#pragma unroll
        for (int off = 16; off; off >>= 1) loc += __shfl_xor_sync(~0u, loc, off);
    }
    if (lane == 0) esm[warp_l] = loc;
    __syncthreads();
    if (threadIdx.x == 0) {
        float t = 0.f;
        for (int w = 0; w < 8; w++) t += esm[w];
        atomicAdd(&d_E, (double)t);
    }
}

__global__ void k_sumcnt() {
    __shared__ float sm[8];
    int i = blockIdx.x * blockDim.x + threadIdx.x;
    float v = (i < BN) ? (float)d_csr_cnt[i] : 0.f;
#pragma unroll
    for (int off = 16; off; off >>= 1) v += __shfl_xor_sync(~0u, v, off);
    int wid = threadIdx.x >> 5, lane = threadIdx.x & 31;
    if (lane == 0) sm[wid] = v;
    __syncthreads();
    if (threadIdx.x == 0) {
        float t = 0.f;
        for (int w = 0; w < 8; w++) t += sm[w];
        atomicAdd(&d_nnz, (double)t);
    }
}

__global__ void k_sumsq() {
    __shared__ float sm[8];
    int i = blockIdx.x * blockDim.x + threadIdx.x;
    float x = (i < Bt * Dt * Dt) ? d_StS[i] : 0.f;
    float v = x * x;
#pragma unroll
    for (int off = 16; off; off >>= 1) v += __shfl_xor_sync(~0u, v, off);
    int wid = threadIdx.x >> 5, lane = threadIdx.x & 31;
    if (lane == 0) sm[wid] = v;
    __syncthreads();
    if (threadIdx.x == 0) {
        float t = 0.f;
        for (int w = 0; w < 8; w++) t += sm[w];
        atomicAdd(&d_F, (double)t);
    }
}

__global__ void k_final(float* out) {
    double l2 = d_nnz - 2.0 * d_E + d_F;
    if (l2 < 0.0) l2 = 0.0;
    out[2 * Bt * Dt * Dt]     = (float)(sqrt(l2) / ((double)Bt * Nt * Nt));
    out[2 * Bt * Dt * Dt + 1] = (float)(d_ent / (double)BN);
}

// ---------------- launch ----------------

extern "C" void kernel_launch(void* const* d_in, const int* in_sizes, int n_in,
                              void* d_out, int out_size) {
    const float* x    = (const float*)d_in[0];
    const float* adj  = (const float*)d_in[1];
    const float* We1l = (const float*)d_in[2];
    const float* be1  = (const float*)d_in[3];
    const float* We1r = (const float*)d_in[4];
    const float* We2l = (const float*)d_in[5];
    const float* be2  = (const float*)d_in[6];
    const float* We2r = (const float*)d_in[7];
    const float* Wa1l = (const float*)d_in[8];
    const float* ba1  = (const float*)d_in[9];
    const float* Wa1r = (const float*)d_in[10];
    const float* Wa2l = (const float*)d_in[11];
    const float* ba2  = (const float*)d_in[12];
    const float* Wa2r = (const float*)d_in[13];
    float* out = (float*)d_out;

    void* p;
    cudaGetSymbolAddress(&p, d_agg);  float* agg  = (float*)p;
    cudaGetSymbolAddress(&p, d_h1);   float* h1   = (float*)p;
    cudaGetSymbolAddress(&p, d_a1);   float* a1   = (float*)p;
    cudaGetSymbolAddress(&p, d_hemb); float* hemb = (float*)p;
    cudaGetSymbolAddress(&p, d_S);    float* S    = (float*)p;
    cudaGetSymbolAddress(&p, d_adjS); float* adjS = (float*)p;
    cudaGetSymbolAddress(&p, d_StS);  float* StS  = (float*)p;

    k_clear<<<256, 256>>>(out, out_size);
    k_build<<<BN, 256>>>(adj);

    // agg1 = adj^T x / deg  (shared by emb1 and assign1)
    k_spmm<<<BN / 8, 256>>>(x, agg, 0, 1);
    k_linear<<<BN / 128, 256>>>(agg, x, We1l, be1, We1r, h1);
    k_linear<<<BN / 128, 256>>>(agg, x, Wa1l, ba1, Wa1r, a1);

    // embedding block 2
    k_spmm<<<BN / 8, 256>>>(h1, agg, 0, 1);
    k_linear<<<BN / 128, 256>>>(agg, h1, We2l, be2, We2r, hemb);

    // assignment block 2
    k_spmm<<<BN / 8, 256>>>(a1, agg, 0, 1);
    k_linear<<<BN / 128, 256>>>(agg, a1, Wa2l, ba2, Wa2r, S);

    k_softmax_ent<<<BN / 8, 256>>>(S);

    // adjS = adj @ S (row gather via CSR, no scaling)
    k_spmm<<<BN / 8, 256>>>(S, adjS, 1, 0);

    // pooled outputs (atomic-accumulated, pre-zeroed)
    k_atb<<<dim3(Nt / (AR * AI), Bt), 256>>>(S, hemb, out);                   // h_pooled
    k_atb<<<dim3(Nt / (AR * AI), Bt), 256>>>(S, adjS, out + Bt * Dt * Dt);    // adj_pooled
    k_atb<<<dim3(Nt / (AR * AI), Bt), 256>>>(S, S, StS);                      // S^T S for link loss

    k_edgedot<<<BN / 8, 256>>>(S);
    k_sumcnt<<<BN / 256, 256>>>();
    k_sumsq<<<(Bt * Dt * Dt) / 256, 256>>>();
    k_final<<<1, 1>>>(out);
}

// round 5
// speedup vs baseline: 1.3024x; 1.0044x over previous
#include <cuda_runtime.h>
#include <math.h>

#define Bt 8
#define Nt 2048
#define Dt 128
#define BN 16384           // Bt*Nt
#define CAP 96             // max in/out degree capacity (mean ~20.5, sigma ~4.5)

typedef unsigned long long ull;

// ---------------- scratch (static device allocations, allowed) ----------------
__device__ int   d_csc_cnt[BN];
__device__ int   d_csr_cnt[BN];
__device__ int   d_csc_idx[BN * CAP];
__device__ int   d_csr_idx[BN * CAP];
__device__ float d_h1  [BN * Dt];
__device__ float d_a1  [BN * Dt];
__device__ float d_hemb[BN * Dt];
__device__ float d_S   [BN * Dt];
__device__ float d_adjS[BN * Dt];
__device__ float d_StS [Bt * Dt * Dt];
// tf32x2 split (hi,lo) planes
__device__ uint2 d_x2  [BN * Dt];
__device__ uint2 d_agg2[BN * Dt];
__device__ uint2 d_h1s [BN * Dt];
__device__ uint2 d_a1s [BN * Dt];
__device__ uint2 d_Ws[4][2 * Dt * Dt];   // per layer: Wl rows 0..127, Wr rows 128..255
__device__ double d_E, d_F, d_nnz, d_ent;

__device__ __forceinline__ uint2 split_tf32(float v) {
    unsigned hi, lo;
    asm("cvt.rna.tf32.f32 %0, %1;" : "=r"(hi) : "f"(v));
    float rem = v - __uint_as_float(hi);
    asm("cvt.rna.tf32.f32 %0, %1;" : "=r"(lo) : "f"(rem));
    return make_uint2(hi, lo);
}

// ---------------- kernels ----------------

__global__ void k_clear(float* out, int osz) {
    int stride = gridDim.x * blockDim.x;
    int i0 = blockIdx.x * blockDim.x + threadIdx.x;
    for (int i = i0; i < BN; i += stride) { d_csc_cnt[i] = 0; d_csr_cnt[i] = 0; }
    for (int i = i0; i < Bt * Dt * Dt; i += stride) d_StS[i] = 0.f;
    for (int i = i0; i < osz; i += stride) out[i] = 0.f;
    if (i0 == 0) { d_E = 0.0; d_F = 0.0; d_nnz = 0.0; d_ent = 0.0; }
}

// split a float array into tf32 (hi,lo)
__global__ void k_split(const float* __restrict__ src, uint2* __restrict__ dst, int n) {
    int i = blockIdx.x * blockDim.x + threadIdx.x;
    if (i * 4 < n) {
        float4 v = *(const float4*)(src + i * 4);
        uint2 s[4] = {split_tf32(v.x), split_tf32(v.y), split_tf32(v.z), split_tf32(v.w)};
        *(uint4*)(dst + i * 4)     = *(uint4*)&s[0];
        *(uint4*)(dst + i * 4 + 2) = *(uint4*)&s[2];
    }
}

// split one (Wl, Wr) pair into d_Ws[layer]
__global__ void k_splitw(const float* __restrict__ Wl, const float* __restrict__ Wr, int layer) {
    int i = blockIdx.x * blockDim.x + threadIdx.x;   // 0 .. 2*Dt*Dt/4-1
    const float* src = (i < Dt * Dt / 4) ? Wl : Wr;
    int off = (i < Dt * Dt / 4) ? i * 4 : (i * 4 - Dt * Dt);
    float4 v = *(const float4*)(src + off);
    uint2 s[4] = {split_tf32(v.x), split_tf32(v.y), split_tf32(v.z), split_tf32(v.w)};
    uint2* dst = d_Ws[layer] + i * 4;
    *(uint4*)(dst)     = *(uint4*)&s[0];
    *(uint4*)(dst + 2) = *(uint4*)&s[2];
}

// one block per adjacency row (b,i); builds CSC (in-edges per target) and CSR (out-edges per source)
__global__ void k_build(const float* __restrict__ adj) {
    int row = blockIdx.x;                 // flat b*Nt + i
    int base = row & ~(Nt - 1);           // b*Nt
    const float4* ar = (const float4*)(adj + (size_t)row * Nt);
    for (int j4 = threadIdx.x; j4 < Nt / 4; j4 += blockDim.x) {
        float4 v = ar[j4];
        int j = j4 << 2;
#pragma unroll
        for (int u = 0; u < 4; u++) {
            float f = (u == 0) ? v.x : (u == 1) ? v.y : (u == 2) ? v.z : v.w;
            if (f != 0.0f) {
                int t = base + j + u;
                int p = atomicAdd(&d_csc_cnt[t], 1);
                if (p < CAP) d_csc_idx[t * CAP + p] = row;
                int q = atomicAdd(&d_csr_cnt[row], 1);
                if (q < CAP) d_csr_idx[row * CAP + q] = t;
            }
        }
    }
}

// warp per output row: acc = (scale? 1/max(deg,1):1) * sum_{s in list[r]} X[s,:]
// writes float (outf) and/or tf32x2 split (out2)
__global__ void k_spmm(const float* __restrict__ X, float* __restrict__ outf,
                       uint2* __restrict__ out2, int use_csr, int scale) {
    int warp = (blockIdx.x * blockDim.x + threadIdx.x) >> 5;
    int lane = threadIdx.x & 31;
    if (warp >= BN) return;
    const int* cntp = use_csr ? d_csr_cnt : d_csc_cnt;
    const int* idxp = use_csr ? d_csr_idx : d_csc_idx;
    int c = cntp[warp];
    int cl = c < CAP ? c : CAP;
    const int* ip = idxp + warp * CAP;
    float4 acc = make_float4(0.f, 0.f, 0.f, 0.f);
    int e = 0;
    for (; e + 2 <= cl; e += 2) {
        int s0 = ip[e], s1 = ip[e + 1];
        float4 v0 = *(const float4*)(X + (size_t)s0 * Dt + (lane << 2));
        float4 v1 = *(const float4*)(X + (size_t)s1 * Dt + (lane << 2));
        acc.x += v0.x + v1.x; acc.y += v0.y + v1.y;
        acc.z += v0.z + v1.z; acc.w += v0.w + v1.w;
    }
    if (e < cl) {
        int s = ip[e];
        float4 v = *(const float4*)(X + (size_t)s * Dt + (lane << 2));
        acc.x += v.x; acc.y += v.y; acc.z += v.z; acc.w += v.w;
    }
    if (scale) {
        float sc = 1.0f / (float)(c > 1 ? c : 1);
        acc.x *= sc; acc.y *= sc; acc.z *= sc; acc.w *= sc;
    }
    if (outf)
        *(float4*)(outf + (size_t)warp * Dt + (lane << 2)) = acc;
    if (out2) {
        uint2 s[4] = {split_tf32(acc.x), split_tf32(acc.y), split_tf32(acc.z), split_tf32(acc.w)};
        uint2* dp = out2 + (size_t)warp * Dt + (lane << 2);
        *(uint4*)(dp)     = *(uint4*)&s[0];
        *(uint4*)(dp + 2) = *(uint4*)&s[2];
    }
}

// ---------------------------------------------------------------------------
// fused dual-GEMM via tf32x2 tensor cores on PRE-SPLIT inputs:
//   out = l2norm(relu(agg @ Wl^T + b + xin @ Wr^T))
// Block: 64 rows x 128 cols, 256 threads = 8 warps (2M x 4N), warp 32x32.
// acc += Ah*Bh + Ah*Bl + Al*Bh (3 MMA per k8 per tile).
// A fragment order (PTX): a0=(g,k) a1=(g+8,k) a2=(g,k+4) a3=(g+8,k+4).
// ---------------------------------------------------------------------------
#define KSTR 20
#define MMA_TF32(ac, a0, a1, a2, a3, b0, b1) \
    asm volatile("mma.sync.aligned.m16n8k8.row.col.f32.tf32.tf32.f32 " \
        "{%0,%1,%2,%3}, {%4,%5,%6,%7}, {%8,%9}, {%0,%1,%2,%3};" \
        : "+f"((ac)[0]), "+f"((ac)[1]), "+f"((ac)[2]), "+f"((ac)[3]) \
        : "r"(a0), "r"(a1), "r"(a2), "r"(a3), "r"(b0), "r"(b1))

__global__ void __launch_bounds__(256)
k_linear(const uint2* __restrict__ A2a, const uint2* __restrict__ A2b,
         const uint2* __restrict__ W2, const float* __restrict__ bias,
         float* __restrict__ out, uint2* __restrict__ out2) {
    __shared__ uint2 As2[64 * KSTR];     // 10 KB
    __shared__ uint2 Bs2[128 * KSTR];    // 20 KB

    int tx = threadIdx.x;
    int lane = tx & 31;
    int warp = tx >> 5;
    int warpM = warp >> 2;        // 0..1 : rows warpM*32 .. +31
    int warpN = warp & 3;         // 0..3 : cols warpN*32 .. +31
    int lq = lane >> 2;           // 0..7
    int lr = lane & 3;            // 0..3
    int r0 = blockIdx.x * 64;

    float acc[2][4][4];
#pragma unroll
    for (int mi = 0; mi < 2; mi++)
#pragma unroll
        for (int nj = 0; nj < 4; nj++)
#pragma unroll
            for (int q = 0; q < 4; q++) acc[mi][nj][q] = 0.f;

    for (int kc = 0; kc < 16; kc++) {           // 16 chunks of K=16
        const uint2* Asrc = (kc < 8) ? A2a : A2b;
        int wbase = (kc < 8) ? 0 : Dt * Dt;
        int kb = (kc & 7) * 16;
        // A chunk: 64 rows x 16 -> 512 uint4; each thread 2
#pragma unroll
        for (int it = 0; it < 2; it++) {
            int j = tx + it * 256;
            int row = j >> 3, k = (j & 7) << 1;
            uint4 v = *(const uint4*)(Asrc + (size_t)(r0 + row) * Dt + kb + k);
            *(uint4*)&As2[row * KSTR + k] = v;
        }
        // B chunk: 128 rows x 16 -> 1024 uint4; each thread 4
#pragma unroll
        for (int it = 0; it < 4; it++) {
            int j = tx + it * 256;
            int row = j >> 3, k = (j & 7) << 1;
            uint4 v = *(const uint4*)(W2 + wbase + row * Dt + kb + k);
            *(uint4*)&Bs2[row * KSTR + k] = v;
        }
        __syncthreads();
#pragma unroll
        for (int ks = 0; ks < 2; ks++) {
            int k0 = ks * 8;
            uint2 af[2][4];
#pragma unroll
            for (int mi = 0; mi < 2; mi++) {
                int row = warpM * 32 + mi * 16 + lq;
                af[mi][0] = As2[row * KSTR + k0 + lr];            // (g,   k)
                af[mi][1] = As2[(row + 8) * KSTR + k0 + lr];      // (g+8, k)
                af[mi][2] = As2[row * KSTR + k0 + 4 + lr];        // (g,   k+4)
                af[mi][3] = As2[(row + 8) * KSTR + k0 + 4 + lr];  // (g+8, k+4)
            }
            uint2 bf[4][2];
#pragma unroll
            for (int nj = 0; nj < 4; nj++) {
                int n = warpN * 32 + nj * 8 + lq;
                bf[nj][0] = Bs2[n * KSTR + k0 + lr];
                bf[nj][1] = Bs2[n * KSTR + k0 + 4 + lr];
            }
#pragma unroll
            for (int mi = 0; mi < 2; mi++)
#pragma unroll
                for (int nj = 0; nj < 4; nj++) {
                    MMA_TF32(acc[mi][nj],
                             af[mi][0].x, af[mi][1].x, af[mi][2].x, af[mi][3].x,
                             bf[nj][0].x, bf[nj][1].x);
                    MMA_TF32(acc[mi][nj],
                             af[mi][0].x, af[mi][1].x, af[mi][2].x, af[mi][3].x,
                             bf[nj][0].y, bf[nj][1].y);
                    MMA_TF32(acc[mi][nj],
                             af[mi][0].y, af[mi][1].y, af[mi][2].y, af[mi][3].y,
                             bf[nj][0].x, bf[nj][1].x);
                }
        }
        __syncthreads();
    }

    // ---- epilogue: bias + relu + row L2 norm ----
    float* red = (float*)As2;             // [64][4]

    float bv[4][2];
#pragma unroll
    for (int nj = 0; nj < 4; nj++) {
        int col = warpN * 32 + nj * 8 + 2 * lr;
        bv[nj][0] = bias[col];
        bv[nj][1] = bias[col + 1];
    }

    float ss[2][2];
#pragma unroll
    for (int mi = 0; mi < 2; mi++) { ss[mi][0] = 0.f; ss[mi][1] = 0.f; }
#pragma unroll
    for (int mi = 0; mi < 2; mi++)
#pragma unroll
        for (int nj = 0; nj < 4; nj++) {
            float v0 = fmaxf(acc[mi][nj][0] + bv[nj][0], 0.f);
            float v1 = fmaxf(acc[mi][nj][1] + bv[nj][1], 0.f);
            float v2 = fmaxf(acc[mi][nj][2] + bv[nj][0], 0.f);
            float v3 = fmaxf(acc[mi][nj][3] + bv[nj][1], 0.f);
            acc[mi][nj][0] = v0; acc[mi][nj][1] = v1;
            acc[mi][nj][2] = v2; acc[mi][nj][3] = v3;
            ss[mi][0] += v0 * v0 + v1 * v1;
            ss[mi][1] += v2 * v2 + v3 * v3;
        }
#pragma unroll
    for (int mi = 0; mi < 2; mi++)
#pragma unroll
        for (int h = 0; h < 2; h++) {
            float s = ss[mi][h];
            s += __shfl_xor_sync(~0u, s, 1);
            s += __shfl_xor_sync(~0u, s, 2);
            ss[mi][h] = s;
        }
    if (lr == 0) {
#pragma unroll
        for (int mi = 0; mi < 2; mi++)
#pragma unroll
            for (int h = 0; h < 2; h++) {
                int row = warpM * 32 + mi * 16 + lq + h * 8;
                red[row * 4 + warpN] = ss[mi][h];
            }
    }
    __syncthreads();
#pragma unroll
    for (int mi = 0; mi < 2; mi++) {
        int rowA = warpM * 32 + mi * 16 + lq;
        float t0 = red[rowA * 4] + red[rowA * 4 + 1] + red[rowA * 4 + 2] + red[rowA * 4 + 3];
        float t1 = red[(rowA + 8) * 4] + red[(rowA + 8) * 4 + 1] + red[(rowA + 8) * 4 + 2] + red[(rowA + 8) * 4 + 3];
        float inv0 = 1.0f / (sqrtf(t0) + 1e-9f);
        float inv1 = 1.0f / (sqrtf(t1) + 1e-9f);
#pragma unroll
        for (int nj = 0; nj < 4; nj++) {
            int col = warpN * 32 + nj * 8 + 2 * lr;
            float2 o0 = make_float2(acc[mi][nj][0] * inv0, acc[mi][nj][1] * inv0);
            float2 o1 = make_float2(acc[mi][nj][2] * inv1, acc[mi][nj][3] * inv1);
            *(float2*)(out + (size_t)(r0 + rowA) * Dt + col) = o0;
            *(float2*)(out + (size_t)(r0 + rowA + 8) * Dt + col) = o1;
            if (out2) {
                uint2 s0[2] = {split_tf32(o0.x), split_tf32(o0.y)};
                uint2 s1[2] = {split_tf32(o1.x), split_tf32(o1.y)};
                *(uint4*)(out2 + (size_t)(r0 + rowA) * Dt + col) = *(uint4*)&s0[0];
                *(uint4*)(out2 + (size_t)(r0 + rowA + 8) * Dt + col) = *(uint4*)&s1[0];
            }
        }
    }
}

// warp per row: in-place softmax over 128, accumulate entropy
__global__ void k_softmax_ent(float* __restrict__ S) {
    __shared__ float esm[8];
    int warp_l = threadIdx.x >> 5;
    int warp = (blockIdx.x * blockDim.x + threadIdx.x) >> 5;
    int lane = threadIdx.x & 31;
    float ent = 0.f;
    if (warp < BN) {
        float4 v = *(const float4*)(S + (size_t)warp * Dt + (lane << 2));
        float m = fmaxf(fmaxf(v.x, v.y), fmaxf(v.z, v.w));
#pragma unroll
        for (int off = 16; off; off >>= 1) m = fmaxf(m, __shfl_xor_sync(~0u, m, off));
        float e0 = expf(v.x - m), e1 = expf(v.y - m), e2 = expf(v.z - m), e3 = expf(v.w - m);
        float s = e0 + e1 + e2 + e3;
#pragma unroll
        for (int off = 16; off; off >>= 1) s += __shfl_xor_sync(~0u, s, off);
        float inv = 1.0f / s;
        float p0 = e0 * inv, p1 = e1 * inv, p2 = e2 * inv, p3 = e3 * inv;
        ent = -(p0 * logf(p0 + 1e-15f) + p1 * logf(p1 + 1e-15f)
              + p2 * logf(p2 + 1e-15f) + p3 * logf(p3 + 1e-15f));
#pragma unroll
        for (int off = 16; off; off >>= 1) ent += __shfl_xor_sync(~0u, ent, off);
        *(float4*)(S + (size_t)warp * Dt + (lane << 2)) = make_float4(p0, p1, p2, p3);
    }
    if (lane == 0) esm[warp_l] = ent;
    __syncthreads();
    if (threadIdx.x == 0) {
        float t = 0.f;
        for (int w = 0; w < 8; w++) t += esm[w];
        atomicAdd(&d_ent, (double)t);
    }
}

// C[b] += A[b]^T @ B[b]  (A,B: [Nt x 128] per batch, C: [128 x 128] per batch)
#define AR 32
#define AI 4
__global__ void k_atb(const float* __restrict__ A, const float* __restrict__ Bm,
                      float* __restrict__ C) {
    __shared__ float As[AR][Dt];
    __shared__ float Bs[AR][Dt];
    int b = blockIdx.y;
    ull acc[8][4];
#pragma unroll
    for (int i = 0; i < 8; i++)
#pragma unroll
        for (int j = 0; j < 4; j++) acc[i][j] = 0ull;
    int tk = threadIdx.x >> 4, td = threadIdx.x & 15;
    for (int c = 0; c < AI; c++) {
        int n0 = (blockIdx.x * AI + c) * AR;
        const float* Ap = A  + ((size_t)b * Nt + n0) * Dt;
        const float* Bp = Bm + ((size_t)b * Nt + n0) * Dt;
        __syncthreads();
        for (int t = threadIdx.x; t < AR * 32; t += 256) {
            int r = t >> 5, k4 = (t & 31) << 2;
            *(float4*)&As[r][k4] = *(const float4*)(Ap + r * Dt + k4);
            *(float4*)&Bs[r][k4] = *(const float4*)(Bp + r * Dt + k4);
        }
        __syncthreads();
        for (int n = 0; n < AR; n++) {
            float a[8];
            *(float4*)&a[0] = *(const float4*)&As[n][tk * 8];
            *(float4*)&a[4] = *(const float4*)&As[n][tk * 8 + 4];
            const ulonglong2* bp = (const ulonglong2*)&Bs[n][td * 8];
            ulonglong2 b01 = bp[0];
            ulonglong2 b23 = bp[1];
            ull ad[8];
#pragma unroll
            for (int i = 0; i < 8; i++) {
                unsigned int ab = __float_as_uint(a[i]);
                asm("mov.b64 %0, {%1, %1};" : "=l"(ad[i]) : "r"(ab));
            }
#pragma unroll
            for (int i = 0; i < 8; i++) {
                asm("fma.rn.f32x2 %0, %1, %2, %0;" : "+l"(acc[i][0]) : "l"(ad[i]), "l"(b01.x));
                asm("fma.rn.f32x2 %0, %1, %2, %0;" : "+l"(acc[i][1]) : "l"(ad[i]), "l"(b01.y));
                asm("fma.rn.f32x2 %0, %1, %2, %0;" : "+l"(acc[i][2]) : "l"(ad[i]), "l"(b23.x));
                asm("fma.rn.f32x2 %0, %1, %2, %0;" : "+l"(acc[i][3]) : "l"(ad[i]), "l"(b23.y));
            }
        }
    }
    size_t cb = (size_t)b * Dt * Dt;
#pragma unroll
    for (int i = 0; i < 8; i++)
#pragma unroll
        for (int j = 0; j < 4; j++) {
            float lo, hi;
            asm("mov.b64 {%0, %1}, %2;" : "=f"(lo), "=f"(hi) : "l"(acc[i][j]));
            atomicAdd(&C[cb + (size_t)(tk * 8 + i) * Dt + (td * 8 + 2 * j)], lo);
            atomicAdd(&C[cb + (size_t)(tk * 8 + i) * Dt + (td * 8 + 2 * j + 1)], hi);
        }
}

// E = sum over edges (n->m) of dot(S[n], S[m]); warp per source row
__global__ void k_edgedot(const float* __restrict__ S) {
    __shared__ float esm[8];
    int warp_l = threadIdx.x >> 5;
    int warp = (blockIdx.x * blockDim.x + threadIdx.x) >> 5;
    int lane = threadIdx.x & 31;
    float loc = 0.f;
    if (warp < BN) {
        float4 sn = *(const float4*)(S + (size_t)warp * Dt + (lane << 2));
        int c = d_csr_cnt[warp]; if (c > CAP) c = CAP;
        const int* ip = d_csr_idx + warp * CAP;
        for (int e = 0; e < c; e++) {
            int mrow = ip[e];
            float4 sm = *(const float4*)(S + (size_t)mrow * Dt + (lane << 2));
            loc += sn.x * sm.x + sn.y * sm.y + sn.z * sm.z + sn.w * sm.w;
        }
#pragma unroll
        for (int off = 16; off; off >>= 1) loc += __shfl_xor_sync(~0u, loc, off);
    }
    if (lane == 0) esm[warp_l] = loc;
    __syncthreads();
    if (threadIdx.x == 0) {
        float t = 0.f;
        for (int w = 0; w < 8; w++) t += esm[w];
        atomicAdd(&d_E, (double)t);
    }
}

__global__ void k_sumcnt() {
    __shared__ float sm[8];
    int i = blockIdx.x * blockDim.x + threadIdx.x;
    float v = (i < BN) ? (float)d_csr_cnt[i] : 0.f;
#pragma unroll
    for (int off = 16; off; off >>= 1) v += __shfl_xor_sync(~0u, v, off);
    int wid = threadIdx.x >> 5, lane = threadIdx.x & 31;
    if (lane == 0) sm[wid] = v;
    __syncthreads();
    if (threadIdx.x == 0) {
        float t = 0.f;
        for (int w = 0; w < 8; w++) t += sm[w];
        atomicAdd(&d_nnz, (double)t);
    }
}

__global__ void k_sumsq() {
    __shared__ float sm[8];
    int i = blockIdx.x * blockDim.x + threadIdx.x;
    float x = (i < Bt * Dt * Dt) ? d_StS[i] : 0.f;
    float v = x * x;
#pragma unroll
    for (int off = 16; off; off >>= 1) v += __shfl_xor_sync(~0u, v, off);
    int wid = threadIdx.x >> 5, lane = threadIdx.x & 31;
    if (lane == 0) sm[wid] = v;
    __syncthreads();
    if (threadIdx.x == 0) {
        float t = 0.f;
        for (int w = 0; w < 8; w++) t += sm[w];
        atomicAdd(&d_F, (double)t);
    }
}

__global__ void k_final(float* out) {
    double l2 = d_nnz - 2.0 * d_E + d_F;
    if (l2 < 0.0) l2 = 0.0;
    out[2 * Bt * Dt * Dt]     = (float)(sqrt(l2) / ((double)Bt * Nt * Nt));
    out[2 * Bt * Dt * Dt + 1] = (float)(d_ent / (double)BN);
}

// ---------------- launch ----------------

extern "C" void kernel_launch(void* const* d_in, const int* in_sizes, int n_in,
                              void* d_out, int out_size) {
    const float* x    = (const float*)d_in[0];
    const float* adj  = (const float*)d_in[1];
    const float* We1l = (const float*)d_in[2];
    const float* be1  = (const float*)d_in[3];
    const float* We1r = (const float*)d_in[4];
    const float* We2l = (const float*)d_in[5];
    const float* be2  = (const float*)d_in[6];
    const float* We2r = (const float*)d_in[7];
    const float* Wa1l = (const float*)d_in[8];
    const float* ba1  = (const float*)d_in[9];
    const float* Wa1r = (const float*)d_in[10];
    const float* Wa2l = (const float*)d_in[11];
    const float* ba2  = (const float*)d_in[12];
    const float* Wa2r = (const float*)d_in[13];
    float* out = (float*)d_out;

    void* p;
    cudaGetSymbolAddress(&p, d_h1);   float* h1   = (float*)p;
    cudaGetSymbolAddress(&p, d_a1);   float* a1   = (float*)p;
    cudaGetSymbolAddress(&p, d_hemb); float* hemb = (float*)p;
    cudaGetSymbolAddress(&p, d_S);    float* S    = (float*)p;
    cudaGetSymbolAddress(&p, d_adjS); float* adjS = (float*)p;
    cudaGetSymbolAddress(&p, d_StS);  float* StS  = (float*)p;
    cudaGetSymbolAddress(&p, d_x2);   uint2* x2   = (uint2*)p;
    cudaGetSymbolAddress(&p, d_agg2); uint2* agg2 = (uint2*)p;
    cudaGetSymbolAddress(&p, d_h1s);  uint2* h1s  = (uint2*)p;
    cudaGetSymbolAddress(&p, d_a1s);  uint2* a1s  = (uint2*)p;
    cudaGetSymbolAddress(&p, d_Ws);   uint2* Ws   = (uint2*)p;

    k_clear<<<256, 256>>>(out, out_size);
    k_build<<<BN, 256>>>(adj);

    // one-time splits
    k_split<<<(BN * Dt / 4 + 255) / 256, 256>>>(x, x2, BN * Dt);
    k_splitw<<<(2 * Dt * Dt / 4) / 256, 256>>>(We1l, We1r, 0);
    k_splitw<<<(2 * Dt * Dt / 4) / 256, 256>>>(Wa1l, Wa1r, 1);
    k_splitw<<<(2 * Dt * Dt / 4) / 256, 256>>>(We2l, We2r, 2);
    k_splitw<<<(2 * Dt * Dt / 4) / 256, 256>>>(Wa2l, Wa2r, 3);

    // agg1 = adj^T x / deg  (shared by emb1 and assign1), split form
    k_spmm<<<BN / 8, 256>>>(x, nullptr, agg2, 0, 1);
    k_linear<<<BN / 64, 256>>>(agg2, x2, Ws + 0 * 2 * Dt * Dt, be1, h1, h1s);
    k_linear<<<BN / 64, 256>>>(agg2, x2, Ws + 1 * 2 * Dt * Dt, ba1, a1, a1s);

    // embedding block 2
    k_spmm<<<BN / 8, 256>>>(h1, nullptr, agg2, 0, 1);
    k_linear<<<BN / 64, 256>>>(agg2, h1s, Ws + 2 * 2 * Dt * Dt, be2, hemb, nullptr);

    // assignment block 2
    k_spmm<<<BN / 8, 256>>>(a1, nullptr, agg2, 0, 1);
    k_linear<<<BN / 64, 256>>>(agg2, a1s, Ws + 3 * 2 * Dt * Dt, ba2, S, nullptr);

    k_softmax_ent<<<BN / 8, 256>>>(S);

    // adjS = adj @ S (row gather via CSR, no scaling)
    k_spmm<<<BN / 8, 256>>>(S, adjS, nullptr, 1, 0);

    // pooled outputs (atomic-accumulated, pre-zeroed)
    k_atb<<<dim3(Nt / (AR * AI), Bt), 256>>>(S, hemb, out);                   // h_pooled
    k_atb<<<dim3(Nt / (AR * AI), Bt), 256>>>(S, adjS, out + Bt * Dt * Dt);    // adj_pooled
    k_atb<<<dim3(Nt / (AR * AI), Bt), 256>>>(S, S, StS);                      // S^T S for link loss

    k_edgedot<<<BN / 8, 256>>>(S);
    k_sumcnt<<<BN / 256, 256>>>();
    k_sumsq<<<(Bt * Dt * Dt) / 256, 256>>>();
    k_final<<<1, 1>>>(out);
}